// round 11
// baseline (speedup 1.0000x reference)
#include <cuda_runtime.h>

#define NN   50000
#define NE   640000
#define HID  128
#define NG   20
#define EF   4
#define XOUT_OFF (NN*HID)

typedef unsigned long long u64;

// scratch
__device__ __align__(16) float g_mi[NN*HID];
__device__ __align__(16) float g_p [NN*HID];
__device__ __align__(16) float g_q [NN*HID];
__device__ __align__(16) float g_dx[NN*3];

__device__ __forceinline__ float sigmoidf_(float v){ return 1.f/(1.f+__expf(-v)); }
__device__ __forceinline__ float siluf_(float v){ return v/(1.f+__expf(-v)); }
__device__ __forceinline__ int clampi(int v){ return v < 0 ? 0 : (v >= NN ? NN-1 : v); }
__device__ __forceinline__ float4 ld4(const float* p){ return *(const float4*)p; }

__device__ __forceinline__ void red_add_v4(float* a, float x, float y, float z, float w){
    asm volatile("red.global.add.v4.f32 [%0], {%1,%2,%3,%4};"
                 :: "l"(a), "f"(x), "f"(y), "f"(z), "f"(w) : "memory");
}

#define PK2(d,lo,hi)  asm("mov.b64 %0, {%1,%2};" : "=l"(d) : "f"(lo), "f"(hi))
#define UPK2(lo,hi,s) asm("mov.b64 {%0,%1}, %2;" : "=f"(lo), "=f"(hi) : "l"(s))
#define FMA2(d,a,b)   asm("fma.rn.f32x2 %0, %1, %2, %0;" : "+l"(d) : "l"(a), "l"(b))

__device__ __forceinline__ unsigned smem_u32(const void* p){
    unsigned a;
    asm("{ .reg .u64 t; cvta.to.shared.u64 t, %1; cvt.u32.u64 %0, t; }" : "=r"(a) : "l"(p));
    return a;
}
__device__ __forceinline__ void lds2u64(u64& a, u64& b, unsigned addr){
    asm volatile("ld.shared.v2.u64 {%0,%1}, [%2];" : "=l"(a), "=l"(b) : "r"(addr));
}
__device__ __forceinline__ void sts_u64(unsigned addr, u64 v){
    asm volatile("st.shared.u64 [%0], %1;" :: "r"(addr), "l"(v));
}
__device__ __forceinline__ void cpa16(unsigned saddr, const float* g){
    asm volatile("cp.async.ca.shared.global [%0], [%1], 16;" :: "r"(saddr), "l"(g));
}
#define CPC()  asm volatile("cp.async.commit_group;" ::: "memory")
#define CPW(n) asm volatile("cp.async.wait_group %0;" :: "n"(n) : "memory")

// async stage: 32 rows x 128 floats = 1024 f4
template<int NTH>
__device__ __forceinline__ void stage_async(unsigned wsu, const float* Wg, int kb, int t){
    const float* src = Wg + kb*128;
    #pragma unroll
    for (int i=0;i<1024/NTH;i++)
        cpa16(wsu + (unsigned)(t + NTH*i)*16u, src + (t + NTH*i)*4);
    CPC();
}

__global__ void zero_kernel() {
    int i = blockIdx.x*256 + threadIdx.x;
    if (i < NN*HID/4) ((float4*)g_mi)[i] = make_float4(0.f,0.f,0.f,0.f);
    if (i < NN*3/4)   ((float4*)g_dx)[i] = make_float4(0.f,0.f,0.f,0.f);
}

// ---------------- FFMA2 mainloops ----------------
// 8 rows x 8 cols per thread (edge/pre)
template<int KC, int LD4, bool SWZ>
__device__ __forceinline__ void gemm_main(unsigned asu, const float4* __restrict__ ws4,
                                          int tx, int ty, u64 acc[4][8], int kbase)
{
    #pragma unroll 8
    for (int kk = 0; kk < KC; ++kk) {
        int k = kbase + kk;
        int swz = SWZ ? ((k>>3)&7) : 0;
        u64 a01,a23,a45,a67;
        lds2u64(a01,a23, asu + (unsigned)(k*LD4 + ((2*ty)  ^swz))*16u);
        lds2u64(a45,a67, asu + (unsigned)(k*LD4 + ((2*ty+1)^swz))*16u);
        float4 w0 = ws4[kk*32 + 2*tx], w1 = ws4[kk*32 + 2*tx + 1];
        float wv[8] = {w0.x,w0.y,w0.z,w0.w,w1.x,w1.y,w1.z,w1.w};
        u64 wp[8];
        #pragma unroll
        for (int j=0;j<8;j++) PK2(wp[j], wv[j], wv[j]);
        #pragma unroll
        for (int j=0;j<8;j++){
            FMA2(acc[0][j], a01, wp[j]);
            FMA2(acc[1][j], a23, wp[j]);
            FMA2(acc[2][j], a45, wp[j]);
            FMA2(acc[3][j], a67, wp[j]);
        }
    }
}
// 8 rows x 4 cols per thread (node): tx 0..31, ty 0..7
template<int KC, int LD4, bool SWZ>
__device__ __forceinline__ void gemm_main4(unsigned asu, const float4* __restrict__ ws4,
                                           int tx, int ty, u64 acc[4][4], int kbase)
{
    #pragma unroll 8
    for (int kk = 0; kk < KC; ++kk) {
        int k = kbase + kk;
        int swz = SWZ ? ((k>>3)&7) : 0;
        u64 a01,a23,a45,a67;
        lds2u64(a01,a23, asu + (unsigned)(k*LD4 + ((2*ty)  ^swz))*16u);
        lds2u64(a45,a67, asu + (unsigned)(k*LD4 + ((2*ty+1)^swz))*16u);
        float4 w0 = ws4[kk*32 + tx];
        float wv[4] = {w0.x,w0.y,w0.z,w0.w};
        u64 wp[4];
        #pragma unroll
        for (int j=0;j<4;j++) PK2(wp[j], wv[j], wv[j]);
        #pragma unroll
        for (int j=0;j<4;j++){
            FMA2(acc[0][j], a01, wp[j]);
            FMA2(acc[1][j], a23, wp[j]);
            FMA2(acc[2][j], a45, wp[j]);
            FMA2(acc[3][j], a67, wp[j]);
        }
    }
}
__device__ __forceinline__ void zacc4x8(u64 acc[4][8]){
    #pragma unroll
    for (int p=0;p<4;p++)
        #pragma unroll
        for (int j=0;j<8;j++) acc[p][j]=0ull;
}
__device__ __forceinline__ void zacc4x4(u64 acc[4][4]){
    #pragma unroll
    for (int p=0;p<4;p++)
        #pragma unroll
        for (int j=0;j<4;j++) acc[p][j]=0ull;
}
template<int NF, int NT>
__device__ __forceinline__ void stage_ld(float4 w[NF], const float* Wg, int kb, int t){
    const float4* Wg4 = (const float4*)(Wg + kb*128);
    #pragma unroll
    for (int i=0;i<NF;i++) w[i] = Wg4[t + NT*i];
}
template<int NF, int NT>
__device__ __forceinline__ void stage_st(float4* ws4, const float4 w[NF], int t){
    #pragma unroll
    for (int i=0;i<NF;i++) ws4[t + NT*i] = w[i];
}
// transposed store of rowpair p for column k (LD4-stride buffer, swizzled)
template<int LD4>
__device__ __forceinline__ unsigned colk_addr(unsigned su, int k, int ty, int p){
    int swz = (k>>3)&7;
    return su + (unsigned)(k*LD4 + ((2*ty + (p>>1)) ^ swz))*16u + (unsigned)(p&1)*8u;
}

// ---------------- pre: P = h@We1[0:128], Q = h@We1[128:256] ----------------
#define PRE_SMEM ((128*68 + 32*128)*4)
__global__ __launch_bounds__(128,4) void pre_kernel(
    const float* __restrict__ h, const float* __restrict__ We1)
{
    extern __shared__ float sm[];
    float*  hs  = sm;
    float4* ws4 = (float4*)(sm + 128*68);
    const int t = threadIdx.x;
    const int tx = t & 15, ty = t >> 4;      // ty 0..7
    const int c0 = 8*tx, r0 = 8*ty;
    const int n0 = blockIdx.x * 64;
    const unsigned su = smem_u32(sm);

    for (int i = t; i < 64*128; i += 128) {
        int e = i >> 7, k = i & 127;
        int node = n0 + e;
        hs[k*68 + e] = (node < NN) ? h[node*HID + k] : 0.f;
    }

    u64 acc[4][8];
    float lo[8], hi[8];
    float4 wa[8];
    stage_ld<8,128>(wa, We1, 0, t);

    #pragma unroll
    for (int g=0; g<2; g++) {
        const float* Wg = g ? (We1 + 128*128) : We1;
        float* dst = g ? g_q : g_p;
        zacc4x8(acc);
        #pragma unroll
        for (int s=0; s<4; s++) {
            __syncthreads();
            stage_st<8,128>(ws4, wa, t);
            if (s < 3)      stage_ld<8,128>(wa, Wg, 32*(s+1), t);
            else if (g==0)  stage_ld<8,128>(wa, We1 + 128*128, 0, t);
            __syncthreads();
            gemm_main<32,17,false>(su, ws4, tx, ty, acc, 32*s);
        }
        #pragma unroll
        for (int p=0;p<4;p++) {
            #pragma unroll
            for (int j=0;j<8;j++) UPK2(lo[j], hi[j], acc[p][j]);
            int nA = n0 + r0 + 2*p, nB = nA + 1;
            if (nA < NN) {
                *(float4*)(dst + nA*HID + c0)   = make_float4(lo[0],lo[1],lo[2],lo[3]);
                *(float4*)(dst + nA*HID + c0+4) = make_float4(lo[4],lo[5],lo[6],lo[7]);
            }
            if (nB < NN) {
                *(float4*)(dst + nB*HID + c0)   = make_float4(hi[0],hi[1],hi[2],hi[3]);
                *(float4*)(dst + nB*HID + c0+4) = make_float4(hi[4],hi[5],hi[6],hi[7]);
            }
        }
    }
}

// ---------------- edge kernel: cp.async double-buffered staging ------------
// t1s [128 cols][33 f4] @0 | wsA @16896 (4096 f) | wsB @20992 (4096 f)
#define EDGE_SMEM ((16896 + 4096 + 4096)*4)
__global__ __launch_bounds__(256,2) void edge_kernel(
    const float* __restrict__ x,
    const int* __restrict__ eidx, const float* __restrict__ edge_attr,
    const float* __restrict__ We1, const float* __restrict__ be1,
    const float* __restrict__ We2, const float* __restrict__ be2,
    const float* __restrict__ Winf, const float* __restrict__ binf,
    const float* __restrict__ Wx1, const float* __restrict__ bx1,
    const float* __restrict__ Wx2)
{
    extern __shared__ float sm[];
    float*  fe   = sm;                        // [24][132] aliases t1s
    float4* wsA4 = (float4*)(sm + 16896);
    float4* wsB4 = (float4*)(sm + 20992);
    __shared__ int   dstl[128], srcl[128];
    __shared__ float rels[3][128], dsv[128];
    __shared__ float be1s[128], be2s[128], bx1s[128], winfs[128], wx2s[128];

    const int t  = threadIdx.x;
    const int tx = t & 15, ty = t >> 4;
    const int c0 = 8*tx, r0 = 8*ty;
    const long e0 = (long)blockIdx.x * 128;
    const unsigned t1su = smem_u32(sm);
    const unsigned wsAu = t1su + 16896u*4u;
    const unsigned wsBu = t1su + 20992u*4u;

    // async: We1 remainder (24x128 = 768 f4) -> wsA ; We2 s0 -> wsB
    {
        const float* src = We1 + 256*128;
        #pragma unroll
        for (int i=0;i<3;i++) cpa16(wsAu + (unsigned)(t+256*i)*16u, src + (t+256*i)*4);
        CPC();
    }
    stage_async<256>(wsBu, We2, 0, t);

    if (t < 128) {
        int s = clampi(eidx[e0 + t]);
        int d = clampi(eidx[NE + e0 + t]);
        srcl[t] = s; dstl[t] = d;
        float d0 = x[d*3+0]-x[s*3+0];
        float d1 = x[d*3+1]-x[s*3+1];
        float d2 = x[d*3+2]-x[s*3+2];
        rels[0][t]=d0; rels[1][t]=d1; rels[2][t]=d2;
        dsv[t] = sqrtf(d0*d0 + d1*d1 + d2*d2 + 1e-8f);
        be1s[t]=be1[t]; be2s[t]=be2[t]; bx1s[t]=bx1[t];
        winfs[t]=Winf[t]; wx2s[t]=Wx2[t];
    }
    __syncthreads();

    // feature tile fe[24][132]: gauss(d)[20] | edge_attr[4]
    const float step  = 10.f/19.f;
    const float coeff = -0.5f/(step*step);
    for (int i = t; i < 24*128; i += 256) {
        int e = i & 127, k = i >> 7;
        float v;
        if (k < NG) { float dd = dsv[e] - step*(float)k; v = __expf(coeff*dd*dd); }
        else        { v = edge_attr[(e0+e)*EF + (k-NG)]; }
        fe[k*132 + e] = v;
    }
    CPW(1);                                   // We1r in wsA
    __syncthreads();

    u64 acc[4][8];
    float lo[8], hi[8];

    // ---- GEMM1 (K=24, wsA) ----
    zacc4x8(acc);
    gemm_main<24,33,false>(t1su, wsA4, tx, ty, acc, 0);
    __syncthreads();                          // wsA + fe free
    stage_async<256>(wsAu, We2, 32, t);       // queue: [We2s0, We2s1]

    // epilogue1: + P[dst] + Q[src] + be1 -> silu -> t1s (transposed, swizzled)
    #pragma unroll
    for (int p=0;p<4;p++) {
        #pragma unroll
        for (int j=0;j<8;j++) UPK2(lo[j], hi[j], acc[p][j]);
        int mA = r0 + 2*p, mB = mA + 1;
        {
            int dn = dstl[mA], sn = srcl[mA];
            float4 p0 = ld4(g_p + dn*HID + c0), p1 = ld4(g_p + dn*HID + c0 + 4);
            float4 q0 = ld4(g_q + sn*HID + c0), q1 = ld4(g_q + sn*HID + c0 + 4);
            lo[0]=siluf_(lo[0]+p0.x+q0.x+be1s[c0+0]); lo[1]=siluf_(lo[1]+p0.y+q0.y+be1s[c0+1]);
            lo[2]=siluf_(lo[2]+p0.z+q0.z+be1s[c0+2]); lo[3]=siluf_(lo[3]+p0.w+q0.w+be1s[c0+3]);
            lo[4]=siluf_(lo[4]+p1.x+q1.x+be1s[c0+4]); lo[5]=siluf_(lo[5]+p1.y+q1.y+be1s[c0+5]);
            lo[6]=siluf_(lo[6]+p1.z+q1.z+be1s[c0+6]); lo[7]=siluf_(lo[7]+p1.w+q1.w+be1s[c0+7]);
        }
        {
            int dn = dstl[mB], sn = srcl[mB];
            float4 p0 = ld4(g_p + dn*HID + c0), p1 = ld4(g_p + dn*HID + c0 + 4);
            float4 q0 = ld4(g_q + sn*HID + c0), q1 = ld4(g_q + sn*HID + c0 + 4);
            hi[0]=siluf_(hi[0]+p0.x+q0.x+be1s[c0+0]); hi[1]=siluf_(hi[1]+p0.y+q0.y+be1s[c0+1]);
            hi[2]=siluf_(hi[2]+p0.z+q0.z+be1s[c0+2]); hi[3]=siluf_(hi[3]+p0.w+q0.w+be1s[c0+3]);
            hi[4]=siluf_(hi[4]+p1.x+q1.x+be1s[c0+4]); hi[5]=siluf_(hi[5]+p1.y+q1.y+be1s[c0+5]);
            hi[6]=siluf_(hi[6]+p1.z+q1.z+be1s[c0+6]); hi[7]=siluf_(hi[7]+p1.w+q1.w+be1s[c0+7]);
        }
        #pragma unroll
        for (int j=0;j<8;j++) {
            u64 v; PK2(v, lo[j], hi[j]);
            sts_u64(colk_addr<33>(t1su, c0+j, ty, p), v);
        }
    }
    CPW(1); __syncthreads();                  // We2s0 + t1s ready

    // ---- GEMM2 (K=128, 4 stages) ----
    zacc4x8(acc);
    gemm_main<32,33,true>(t1su, wsB4, tx, ty, acc, 0);
    __syncthreads();
    stage_async<256>(wsBu, We2, 64, t);
    CPW(1); __syncthreads();
    gemm_main<32,33,true>(t1su, wsA4, tx, ty, acc, 32);
    __syncthreads();
    stage_async<256>(wsAu, We2, 96, t);
    CPW(1); __syncthreads();
    gemm_main<32,33,true>(t1su, wsB4, tx, ty, acc, 64);
    __syncthreads();
    stage_async<256>(wsBu, Wx1, 0, t);
    CPW(1); __syncthreads();
    gemm_main<32,33,true>(t1su, wsA4, tx, ty, acc, 96);
    __syncthreads();                          // all t1s reads done
    stage_async<256>(wsAu, Wx1, 32, t);

    // epilogue2: silu, eij, scatter, rewrite t1s with mij
    {
        float bi = binf[0];
        #pragma unroll
        for (int p=0;p<4;p++) {
            #pragma unroll
            for (int j=0;j<8;j++) UPK2(lo[j], hi[j], acc[p][j]);
            #pragma unroll
            for (int j=0;j<8;j++) {
                lo[j] = siluf_(lo[j] + be2s[c0+j]);
                hi[j] = siluf_(hi[j] + be2s[c0+j]);
            }
            float sA = 0.f, sB = 0.f;
            #pragma unroll
            for (int j=0;j<8;j++) { sA += lo[j]*winfs[c0+j]; sB += hi[j]*winfs[c0+j]; }
            #pragma unroll
            for (int off=8; off; off >>= 1) {
                sA += __shfl_xor_sync(0xffffffffu, sA, off);
                sB += __shfl_xor_sync(0xffffffffu, sB, off);
            }
            int mA = r0 + 2*p, mB = mA + 1;
            float egA = sigmoidf_(sA + bi), egB = sigmoidf_(sB + bi);
            int dnA = dstl[mA], dnB = dstl[mB];
            red_add_v4(&g_mi[dnA*HID + c0],     lo[0]*egA, lo[1]*egA, lo[2]*egA, lo[3]*egA);
            red_add_v4(&g_mi[dnA*HID + c0 + 4], lo[4]*egA, lo[5]*egA, lo[6]*egA, lo[7]*egA);
            red_add_v4(&g_mi[dnB*HID + c0],     hi[0]*egB, hi[1]*egB, hi[2]*egB, hi[3]*egB);
            red_add_v4(&g_mi[dnB*HID + c0 + 4], hi[4]*egB, hi[5]*egB, hi[6]*egB, hi[7]*egB);
            #pragma unroll
            for (int j=0;j<8;j++) {
                u64 v; PK2(v, lo[j], hi[j]);
                sts_u64(colk_addr<33>(t1su, c0+j, ty, p), v);
            }
        }
    }
    CPW(1); __syncthreads();                  // Wx1s0 + t1s(mij) ready

    // ---- GEMM3 (K=128, 4 stages) ----
    zacc4x8(acc);
    gemm_main<32,33,true>(t1su, wsB4, tx, ty, acc, 0);
    __syncthreads();
    stage_async<256>(wsBu, Wx1, 64, t);
    CPW(1); __syncthreads();
    gemm_main<32,33,true>(t1su, wsA4, tx, ty, acc, 32);
    __syncthreads();
    stage_async<256>(wsAu, Wx1, 96, t);
    CPW(1); __syncthreads();
    gemm_main<32,33,true>(t1su, wsB4, tx, ty, acc, 64);
    CPW(0); __syncthreads();
    gemm_main<32,33,true>(t1su, wsA4, tx, ty, acc, 96);

    // epilogue3: xg = tanh(silu(.)·Wx2); coord scatter
    #pragma unroll
    for (int p=0;p<4;p++) {
        #pragma unroll
        for (int j=0;j<8;j++) UPK2(lo[j], hi[j], acc[p][j]);
        float qA = 0.f, qB = 0.f;
        #pragma unroll
        for (int j=0;j<8;j++) {
            float b = bx1s[c0+j], w = wx2s[c0+j];
            qA += siluf_(lo[j] + b)*w;
            qB += siluf_(hi[j] + b)*w;
        }
        #pragma unroll
        for (int off=8; off; off >>= 1) {
            qA += __shfl_xor_sync(0xffffffffu, qA, off);
            qB += __shfl_xor_sync(0xffffffffu, qB, off);
        }
        if (tx < 3) {
            int mA = r0 + 2*p, mB = mA + 1;
            float sA = tanhf(qA) / (dsv[mA] + 1.f);
            float sB = tanhf(qB) / (dsv[mB] + 1.f);
            atomicAdd(&g_dx[dstl[mA]*3 + tx], rels[tx][mA]*sA);
            atomicAdd(&g_dx[dstl[mB]*3 + tx], rels[tx][mB]*sB);
        }
    }
}

// ---------------- node kernel: 256 threads, 8x4 tiles, cp.async ------------
// zs [256 k][17 f4] @0 (unswizzled k-major) | wsA @17408 | wsB @21504
#define NODE_SMEM ((17408 + 4096 + 4096)*4)
__global__ __launch_bounds__(256,2) void node_kernel(
    const float* __restrict__ h, const float* __restrict__ x,
    const float* __restrict__ mask,
    const float* __restrict__ Wn1, const float* __restrict__ bn1,
    const float* __restrict__ Wn2, const float* __restrict__ bn2,
    float* __restrict__ out)
{
    extern __shared__ float sm[];
    float*  zs   = sm;
    float4* wsA4 = (float4*)(sm + 17408);
    float4* wsB4 = (float4*)(sm + 21504);
    const unsigned su   = smem_u32(sm);
    const unsigned wsAu = su + 17408u*4u;
    const unsigned wsBu = su + 21504u*4u;

    const int t  = threadIdx.x;
    const int tx = t & 31, ty = t >> 5;      // tx 0..31, ty 0..7
    const int c0 = 4*tx, r0 = 8*ty;
    const int n0 = blockIdx.x * 64;

    stage_async<256>(wsAu, Wn1, 0, t);
    stage_async<256>(wsBu, Wn1, 32, t);

    for (int i = t; i < 64*256; i += 256) {
        int e = i >> 8, k = i & 255;
        int node = n0 + e;
        float v = 0.f;
        if (node < NN)
            v = (k < HID) ? g_mi[node*HID + k] : h[node*HID + (k-HID)];
        zs[k*68 + e] = v;
    }

    u64 acc[4][4];
    float lo[4], hi[4];

    // ---- GEMM1: K=256, 8 stages (zs unswizzled) ----
    zacc4x4(acc);
    CPW(1); __syncthreads();                   // Wn1 s0 + zs ready
    #pragma unroll
    for (int s=0; s<8; s++) {
        gemm_main4<32,17,false>(su, (s&1)?wsB4:wsA4, tx, ty, acc, 32*s);
        __syncthreads();
        if (s+2 < 8)       stage_async<256>((s&1)?wsBu:wsAu, Wn1, 32*(s+2), t);
        else if (s+2 == 8) stage_async<256>((s&1)?wsBu:wsAu, Wn2, 0, t);
        else               stage_async<256>((s&1)?wsBu:wsAu, Wn2, 32, t);
        if (s < 7) { CPW(1); __syncthreads(); }
    }

    // epilogue1: silu -> rewrite zs cols 0..127 as t1 (swizzled)
    #pragma unroll
    for (int p=0;p<4;p++) {
        #pragma unroll
        for (int j=0;j<4;j++) UPK2(lo[j], hi[j], acc[p][j]);
        #pragma unroll
        for (int j=0;j<4;j++) {
            float b = bn1[c0+j];
            lo[j] = siluf_(lo[j] + b);
            hi[j] = siluf_(hi[j] + b);
        }
        #pragma unroll
        for (int j=0;j<4;j++) {
            u64 v; PK2(v, lo[j], hi[j]);
            sts_u64(colk_addr<17>(su, c0+j, ty, p), v);
        }
    }
    CPW(1); __syncthreads();                   // Wn2 s0 + t1 ready

    // ---- GEMM2: K=128, 4 stages (t1 swizzled) ----
    zacc4x4(acc);
    gemm_main4<32,17,true>(su, wsA4, tx, ty, acc, 0);
    __syncthreads();
    stage_async<256>(wsAu, Wn2, 64, t);
    CPW(1); __syncthreads();
    gemm_main4<32,17,true>(su, wsB4, tx, ty, acc, 32);
    __syncthreads();
    stage_async<256>(wsBu, Wn2, 96, t);
    CPW(1); __syncthreads();
    gemm_main4<32,17,true>(su, wsA4, tx, ty, acc, 64);
    CPW(0); __syncthreads();
    gemm_main4<32,17,true>(su, wsB4, tx, ty, acc, 96);

    #pragma unroll
    for (int p=0;p<4;p++) {
        #pragma unroll
        for (int j=0;j<4;j++) UPK2(lo[j], hi[j], acc[p][j]);
        int nA = n0 + r0 + 2*p, nB = nA + 1;
        if (nA < NN) {
            float4 h0 = ld4(h + nA*HID + c0);
            *(float4*)(out + nA*HID + c0) = make_float4(
                h0.x+lo[0]+bn2[c0+0], h0.y+lo[1]+bn2[c0+1],
                h0.z+lo[2]+bn2[c0+2], h0.w+lo[3]+bn2[c0+3]);
        }
        if (nB < NN) {
            float4 h0 = ld4(h + nB*HID + c0);
            *(float4*)(out + nB*HID + c0) = make_float4(
                h0.x+hi[0]+bn2[c0+0], h0.y+hi[1]+bn2[c0+1],
                h0.z+hi[2]+bn2[c0+2], h0.w+hi[3]+bn2[c0+3]);
        }
    }
    for (int i = t; i < 64*3; i += 256) {
        int e = i/3, a = i - 3*e;
        int node = n0 + e;
        if (node < NN)
            out[XOUT_OFF + node*3 + a] = x[node*3 + a] + g_dx[node*3 + a]*mask[node];
    }
}

extern "C" void kernel_launch(void* const* d_in, const int* in_sizes, int n_in,
                              void* d_out, int out_size)
{
    const float* h         = (const float*)d_in[0];
    const float* x         = (const float*)d_in[1];
    const int*   eidx      = (const int*)d_in[2];   // int32 (jax x64 disabled)
    const float* mask      = (const float*)d_in[3];
    const float* edge_attr = (const float*)d_in[4];
    const float* We1  = (const float*)d_in[5];
    const float* be1  = (const float*)d_in[6];
    const float* We2  = (const float*)d_in[7];
    const float* be2  = (const float*)d_in[8];
    const float* Winf = (const float*)d_in[9];
    const float* binf = (const float*)d_in[10];
    const float* Wx1  = (const float*)d_in[11];
    const float* bx1  = (const float*)d_in[12];
    const float* Wx2  = (const float*)d_in[13];
    const float* Wn1  = (const float*)d_in[14];
    const float* bn1  = (const float*)d_in[15];
    const float* Wn2  = (const float*)d_in[16];
    const float* bn2  = (const float*)d_in[17];
    float* out = (float*)d_out;

    cudaFuncSetAttribute(pre_kernel,  cudaFuncAttributeMaxDynamicSharedMemorySize, PRE_SMEM);
    cudaFuncSetAttribute(edge_kernel, cudaFuncAttributeMaxDynamicSharedMemorySize, EDGE_SMEM);
    cudaFuncSetAttribute(node_kernel, cudaFuncAttributeMaxDynamicSharedMemorySize, NODE_SMEM);

    zero_kernel<<<(NN*HID/4 + 255)/256, 256>>>();
    pre_kernel <<<(NN + 63)/64, 128, PRE_SMEM>>>(h, We1);
    edge_kernel<<<NE/128, 256, EDGE_SMEM>>>(x, eidx, edge_attr,
                                            We1, be1, We2, be2, Winf, binf,
                                            Wx1, bx1, Wx2);
    node_kernel<<<(NN + 63)/64, 256, NODE_SMEM>>>(h, x, mask,
                                                  Wn1, bn1, Wn2, bn2, out);
}

// round 15
// speedup vs baseline: 1.0638x; 1.0638x over previous
#include <cuda_runtime.h>

#define NN   50000
#define NE   640000
#define HID  128
#define NG   20
#define EF   4
#define XOUT_OFF (NN*HID)

typedef unsigned long long u64;

// scratch
__device__ __align__(16) float g_mi[NN*HID];
__device__ __align__(16) float g_p [NN*HID];
__device__ __align__(16) float g_q [NN*HID];
__device__ __align__(16) float g_dx[NN*3];

__device__ __forceinline__ float sigmoidf_(float v){ return 1.f/(1.f+__expf(-v)); }
__device__ __forceinline__ float siluf_(float v){ return v/(1.f+__expf(-v)); }
__device__ __forceinline__ int clampi(int v){ return v < 0 ? 0 : (v >= NN ? NN-1 : v); }
__device__ __forceinline__ float4 ld4(const float* p){ return *(const float4*)p; }

__device__ __forceinline__ void red_add_v4(float* a, float x, float y, float z, float w){
    asm volatile("red.global.add.v4.f32 [%0], {%1,%2,%3,%4};"
                 :: "l"(a), "f"(x), "f"(y), "f"(z), "f"(w) : "memory");
}

#define PK2(d,lo,hi)  asm("mov.b64 %0, {%1,%2};" : "=l"(d) : "f"(lo), "f"(hi))
#define UPK2(lo,hi,s) asm("mov.b64 {%0,%1}, %2;" : "=f"(lo), "=f"(hi) : "l"(s))
#define FMA2(d,a,b)   asm("fma.rn.f32x2 %0, %1, %2, %0;" : "+l"(d) : "l"(a), "l"(b))

__device__ __forceinline__ unsigned smem_u32(const void* p){
    unsigned a;
    asm("{ .reg .u64 t; cvta.to.shared.u64 t, %1; cvt.u32.u64 %0, t; }" : "=r"(a) : "l"(p));
    return a;
}
__device__ __forceinline__ void lds2u64(u64& a, u64& b, unsigned addr){
    asm volatile("ld.shared.v2.u64 {%0,%1}, [%2];" : "=l"(a), "=l"(b) : "r"(addr));
}
__device__ __forceinline__ void sts_u64(unsigned addr, u64 v){
    asm volatile("st.shared.u64 [%0], %1;" :: "r"(addr), "l"(v));
}

__global__ void zero_kernel() {
    int i = blockIdx.x*256 + threadIdx.x;
    if (i < NN*HID/4) ((float4*)g_mi)[i] = make_float4(0.f,0.f,0.f,0.f);
    if (i < NN*3/4)   ((float4*)g_dx)[i] = make_float4(0.f,0.f,0.f,0.f);
}

// ---------------- shared FFMA2 mainloop (8 rows x 8 cols per thread) -------
// cols: {4tx..4tx+3} U {64+4tx..64+4tx+3}  -> W loads are CONTIGUOUS (no
// bank conflicts: w0 = 16 contiguous f4, w1 = next 16).
template<int KC, int LD4, bool SWZ>
__device__ __forceinline__ void gemm_main(unsigned asu, const float4* __restrict__ ws4,
                                          int tx, int ty, u64 acc[4][8], int kbase)
{
    #pragma unroll 8
    for (int kk = 0; kk < KC; ++kk) {
        int k = kbase + kk;
        int swz = SWZ ? ((k>>3)&7) : 0;
        u64 a01,a23,a45,a67;
        lds2u64(a01,a23, asu + (unsigned)(k*LD4 + ((2*ty)  ^swz))*16u);
        lds2u64(a45,a67, asu + (unsigned)(k*LD4 + ((2*ty+1)^swz))*16u);
        float4 w0 = ws4[kk*32 + tx], w1 = ws4[kk*32 + 16 + tx];
        float wv[8] = {w0.x,w0.y,w0.z,w0.w,w1.x,w1.y,w1.z,w1.w};
        u64 wp[8];
        #pragma unroll
        for (int j=0;j<8;j++) PK2(wp[j], wv[j], wv[j]);
        #pragma unroll
        for (int j=0;j<8;j++){
            FMA2(acc[0][j], a01, wp[j]);
            FMA2(acc[1][j], a23, wp[j]);
            FMA2(acc[2][j], a45, wp[j]);
            FMA2(acc[3][j], a67, wp[j]);
        }
    }
}
__device__ __forceinline__ void zacc4x8(u64 acc[4][8]){
    #pragma unroll
    for (int p=0;p<4;p++)
        #pragma unroll
        for (int j=0;j<8;j++) acc[p][j]=0ull;
}
template<int NF, int NT>
__device__ __forceinline__ void stage_ld(float4 w[NF], const float* Wg, int kb, int t){
    const float4* Wg4 = (const float4*)(Wg + kb*128);
    #pragma unroll
    for (int i=0;i<NF;i++) w[i] = Wg4[t + NT*i];
}
template<int NF, int NT>
__device__ __forceinline__ void stage_st(float4* ws4, const float4 w[NF], int t){
    #pragma unroll
    for (int i=0;i<NF;i++) ws4[t + NT*i] = w[i];
}
// transposed store of rowpair p for column k (LD4-stride buffer, swizzled)
template<int LD4>
__device__ __forceinline__ unsigned colk_addr(unsigned su, int k, int ty, int p){
    int swz = (k>>3)&7;
    return su + (unsigned)(k*LD4 + ((2*ty + (p>>1)) ^ swz))*16u + (unsigned)(p&1)*8u;
}

// ---------------- pre: P = h@We1[0:128], Q = h@We1[128:256] ----------------
#define PRE_SMEM ((128*68 + 32*128)*4)
__global__ __launch_bounds__(128,4) void pre_kernel(
    const float* __restrict__ h, const float* __restrict__ We1)
{
    extern __shared__ float sm[];
    float*  hs  = sm;
    float4* ws4 = (float4*)(sm + 128*68);
    const int t = threadIdx.x;
    const int tx = t & 15, ty = t >> 4;      // ty 0..7
    const int cA = 4*tx, cB = 64 + 4*tx, r0 = 8*ty;
    const int n0 = blockIdx.x * 64;
    const unsigned su = smem_u32(sm);

    for (int i = t; i < 64*128; i += 128) {
        int e = i >> 7, k = i & 127;
        int node = n0 + e;
        hs[k*68 + e] = (node < NN) ? h[node*HID + k] : 0.f;
    }

    u64 acc[4][8];
    float lo[8], hi[8];
    float4 wa[8];
    stage_ld<8,128>(wa, We1, 0, t);

    #pragma unroll
    for (int g=0; g<2; g++) {
        const float* Wg = g ? (We1 + 128*128) : We1;
        float* dst = g ? g_q : g_p;
        zacc4x8(acc);
        #pragma unroll
        for (int s=0; s<4; s++) {
            __syncthreads();
            stage_st<8,128>(ws4, wa, t);
            if (s < 3)      stage_ld<8,128>(wa, Wg, 32*(s+1), t);
            else if (g==0)  stage_ld<8,128>(wa, We1 + 128*128, 0, t);
            __syncthreads();
            gemm_main<32,17,false>(su, ws4, tx, ty, acc, 32*s);
        }
        #pragma unroll
        for (int p=0;p<4;p++) {
            #pragma unroll
            for (int j=0;j<8;j++) UPK2(lo[j], hi[j], acc[p][j]);
            int nA = n0 + r0 + 2*p, nB = nA + 1;
            if (nA < NN) {
                *(float4*)(dst + nA*HID + cA) = make_float4(lo[0],lo[1],lo[2],lo[3]);
                *(float4*)(dst + nA*HID + cB) = make_float4(lo[4],lo[5],lo[6],lo[7]);
            }
            if (nB < NN) {
                *(float4*)(dst + nB*HID + cA) = make_float4(hi[0],hi[1],hi[2],hi[3]);
                *(float4*)(dst + nB*HID + cB) = make_float4(hi[4],hi[5],hi[6],hi[7]);
            }
        }
    }
}

// ---------------- edge kernel: 128 edges/CTA, reg-prefetch staging ---------
// t1s [128 cols][33 f4] @0 (16896 floats) | ws [64][128] @16896 (8192 floats)
#define EDGE_SMEM ((16896 + 8192)*4)
__global__ __launch_bounds__(256,2) void edge_kernel(
    const float* __restrict__ x,
    const int* __restrict__ eidx, const float* __restrict__ edge_attr,
    const float* __restrict__ We1, const float* __restrict__ be1,
    const float* __restrict__ We2, const float* __restrict__ be2,
    const float* __restrict__ Winf, const float* __restrict__ binf,
    const float* __restrict__ Wx1, const float* __restrict__ bx1,
    const float* __restrict__ Wx2)
{
    extern __shared__ float sm[];
    float*  fe   = sm;                       // [24][132] aliases t1s
    float4* ws4  = (float4*)(sm + 16896);
    __shared__ int   dstl[128], srcl[128];
    __shared__ float rels[3][128], dsv[128];
    __shared__ float be1s[128], be2s[128], bx1s[128], winfs[128], wx2s[128];

    const int t  = threadIdx.x;
    const int tx = t & 15, ty = t >> 4;
    const int cA = 4*tx, cB = 64 + 4*tx, r0 = 8*ty;
    const long e0 = (long)blockIdx.x * 128;
    const unsigned t1su = smem_u32(sm);

    float4 w1[3], w2[8];
    stage_ld<3,256>(w1, We1 + 256*128, 0, t);

    if (t < 128) {
        int s = clampi(eidx[e0 + t]);
        int d = clampi(eidx[NE + e0 + t]);
        srcl[t] = s; dstl[t] = d;
        float d0 = x[d*3+0]-x[s*3+0];
        float d1 = x[d*3+1]-x[s*3+1];
        float d2 = x[d*3+2]-x[s*3+2];
        rels[0][t]=d0; rels[1][t]=d1; rels[2][t]=d2;
        dsv[t] = sqrtf(d0*d0 + d1*d1 + d2*d2 + 1e-8f);
        be1s[t]=be1[t]; be2s[t]=be2[t]; bx1s[t]=bx1[t];
        winfs[t]=Winf[t]; wx2s[t]=Wx2[t];
    }
    __syncthreads();

    // feature tile fe[24][132]: gauss(d)[20] | edge_attr[4]
    const float step  = 10.f/19.f;
    const float coeff = -0.5f/(step*step);
    for (int i = t; i < 24*128; i += 256) {
        int e = i & 127, k = i >> 7;
        float v;
        if (k < NG) { float dd = dsv[e] - step*(float)k; v = __expf(coeff*dd*dd); }
        else        { v = edge_attr[(e0+e)*EF + (k-NG)]; }
        fe[k*132 + e] = v;
    }
    stage_st<3,256>(ws4, w1, t);
    stage_ld<8,256>(w2, We2, 0, t);          // prefetch GEMM2 s0
    __syncthreads();

    u64 acc[4][8];
    float lo[8], hi[8];

    // ---- GEMM1 (K=24) ----
    zacc4x8(acc);
    gemm_main<24,33,false>(t1su, ws4, tx, ty, acc, 0);
    __syncthreads();                          // ws + fe free
    stage_st<8,256>(ws4, w2, t);
    stage_ld<8,256>(w2, We2, 64, t);          // prefetch GEMM2 s1

    // epilogue1: + P[dst] + Q[src] + be1 -> silu -> t1s (transposed, swizzled)
    #pragma unroll
    for (int p=0;p<4;p++) {
        #pragma unroll
        for (int j=0;j<8;j++) UPK2(lo[j], hi[j], acc[p][j]);
        int mA = r0 + 2*p, mB = mA + 1;
        {
            int dn = dstl[mA], sn = srcl[mA];
            float4 p0 = ld4(g_p + dn*HID + cA), p1 = ld4(g_p + dn*HID + cB);
            float4 q0 = ld4(g_q + sn*HID + cA), q1 = ld4(g_q + sn*HID + cB);
            lo[0]=siluf_(lo[0]+p0.x+q0.x+be1s[cA+0]); lo[1]=siluf_(lo[1]+p0.y+q0.y+be1s[cA+1]);
            lo[2]=siluf_(lo[2]+p0.z+q0.z+be1s[cA+2]); lo[3]=siluf_(lo[3]+p0.w+q0.w+be1s[cA+3]);
            lo[4]=siluf_(lo[4]+p1.x+q1.x+be1s[cB+0]); lo[5]=siluf_(lo[5]+p1.y+q1.y+be1s[cB+1]);
            lo[6]=siluf_(lo[6]+p1.z+q1.z+be1s[cB+2]); lo[7]=siluf_(lo[7]+p1.w+q1.w+be1s[cB+3]);
        }
        {
            int dn = dstl[mB], sn = srcl[mB];
            float4 p0 = ld4(g_p + dn*HID + cA), p1 = ld4(g_p + dn*HID + cB);
            float4 q0 = ld4(g_q + sn*HID + cA), q1 = ld4(g_q + sn*HID + cB);
            hi[0]=siluf_(hi[0]+p0.x+q0.x+be1s[cA+0]); hi[1]=siluf_(hi[1]+p0.y+q0.y+be1s[cA+1]);
            hi[2]=siluf_(hi[2]+p0.z+q0.z+be1s[cA+2]); hi[3]=siluf_(hi[3]+p0.w+q0.w+be1s[cA+3]);
            hi[4]=siluf_(hi[4]+p1.x+q1.x+be1s[cB+0]); hi[5]=siluf_(hi[5]+p1.y+q1.y+be1s[cB+1]);
            hi[6]=siluf_(hi[6]+p1.z+q1.z+be1s[cB+2]); hi[7]=siluf_(hi[7]+p1.w+q1.w+be1s[cB+3]);
        }
        #pragma unroll
        for (int j=0;j<8;j++) {
            u64 v; PK2(v, lo[j], hi[j]);
            int col = (j<4) ? (cA+j) : (cB+j-4);
            sts_u64(colk_addr<33>(t1su, col, ty, p), v);
        }
    }
    __syncthreads();                          // t1s + ws(We2 s0) ready

    // ---- GEMM2 ----
    zacc4x8(acc);
    gemm_main<64,33,true>(t1su, ws4, tx, ty, acc, 0);
    __syncthreads();
    stage_st<8,256>(ws4, w2, t);
    stage_ld<8,256>(w2, Wx1, 0, t);           // prefetch GEMM3 s0
    __syncthreads();
    gemm_main<64,33,true>(t1su, ws4, tx, ty, acc, 64);
    __syncthreads();                          // all t1s reads + ws free
    stage_st<8,256>(ws4, w2, t);
    stage_ld<8,256>(w2, Wx1, 64, t);          // prefetch GEMM3 s1

    // epilogue2: silu, eij, scatter, rewrite t1s with mij
    {
        float bi = binf[0];
        #pragma unroll
        for (int p=0;p<4;p++) {
            #pragma unroll
            for (int j=0;j<8;j++) UPK2(lo[j], hi[j], acc[p][j]);
            #pragma unroll
            for (int j=0;j<8;j++) {
                float b = (j<4) ? be2s[cA+j] : be2s[cB+j-4];
                lo[j] = siluf_(lo[j] + b);
                hi[j] = siluf_(hi[j] + b);
            }
            float sA = 0.f, sB = 0.f;
            #pragma unroll
            for (int j=0;j<8;j++) {
                float w = (j<4) ? winfs[cA+j] : winfs[cB+j-4];
                sA += lo[j]*w; sB += hi[j]*w;
            }
            #pragma unroll
            for (int off=8; off; off >>= 1) {
                sA += __shfl_xor_sync(0xffffffffu, sA, off);
                sB += __shfl_xor_sync(0xffffffffu, sB, off);
            }
            int mA = r0 + 2*p, mB = mA + 1;
            float egA = sigmoidf_(sA + bi), egB = sigmoidf_(sB + bi);
            int dnA = dstl[mA], dnB = dstl[mB];
            red_add_v4(&g_mi[dnA*HID + cA], lo[0]*egA, lo[1]*egA, lo[2]*egA, lo[3]*egA);
            red_add_v4(&g_mi[dnA*HID + cB], lo[4]*egA, lo[5]*egA, lo[6]*egA, lo[7]*egA);
            red_add_v4(&g_mi[dnB*HID + cA], hi[0]*egB, hi[1]*egB, hi[2]*egB, hi[3]*egB);
            red_add_v4(&g_mi[dnB*HID + cB], hi[4]*egB, hi[5]*egB, hi[6]*egB, hi[7]*egB);
            #pragma unroll
            for (int j=0;j<8;j++) {
                u64 v; PK2(v, lo[j], hi[j]);
                int col = (j<4) ? (cA+j) : (cB+j-4);
                sts_u64(colk_addr<33>(t1su, col, ty, p), v);
            }
        }
    }
    __syncthreads();                          // t1s(mij) + ws(Wx1 s0) ready

    // ---- GEMM3 ----
    zacc4x8(acc);
    gemm_main<64,33,true>(t1su, ws4, tx, ty, acc, 0);
    __syncthreads();
    stage_st<8,256>(ws4, w2, t);
    __syncthreads();
    gemm_main<64,33,true>(t1su, ws4, tx, ty, acc, 64);

    // epilogue3: xg = tanh(silu(.)·Wx2); coord scatter
    #pragma unroll
    for (int p=0;p<4;p++) {
        #pragma unroll
        for (int j=0;j<8;j++) UPK2(lo[j], hi[j], acc[p][j]);
        float qA = 0.f, qB = 0.f;
        #pragma unroll
        for (int j=0;j<8;j++) {
            int col = (j<4) ? (cA+j) : (cB+j-4);
            float b = bx1s[col], w = wx2s[col];
            qA += siluf_(lo[j] + b)*w;
            qB += siluf_(hi[j] + b)*w;
        }
        #pragma unroll
        for (int off=8; off; off >>= 1) {
            qA += __shfl_xor_sync(0xffffffffu, qA, off);
            qB += __shfl_xor_sync(0xffffffffu, qB, off);
        }
        if (tx < 3) {
            int mA = r0 + 2*p, mB = mA + 1;
            float sA = tanhf(qA) / (dsv[mA] + 1.f);
            float sB = tanhf(qB) / (dsv[mB] + 1.f);
            atomicAdd(&g_dx[dstl[mA]*3 + tx], rels[tx][mA]*sA);
            atomicAdd(&g_dx[dstl[mB]*3 + tx], rels[tx][mB]*sB);
        }
    }
}

// ---------------- node kernel: 128 threads, 64 nodes/CTA -------------------
// zs [256 k][17 f4] @0 (17408 floats) | ws [32][128] @17408 (4096 floats)
#define NODE_SMEM ((17408 + 4096)*4)
__global__ __launch_bounds__(128,2) void node_kernel(
    const float* __restrict__ h, const float* __restrict__ x,
    const float* __restrict__ mask,
    const float* __restrict__ Wn1, const float* __restrict__ bn1,
    const float* __restrict__ Wn2, const float* __restrict__ bn2,
    float* __restrict__ out)
{
    extern __shared__ float sm[];
    float*  zs  = sm;
    float4* ws4 = (float4*)(sm + 17408);
    const unsigned su = smem_u32(sm);

    const int t  = threadIdx.x;
    const int tx = t & 15, ty = t >> 4;      // ty 0..7
    const int cA = 4*tx, cB = 64 + 4*tx, r0 = 8*ty;
    const int n0 = blockIdx.x * 64;

    for (int i = t; i < 64*256; i += 128) {
        int e = i >> 8, k = i & 255;
        int node = n0 + e;
        float v = 0.f;
        if (node < NN)
            v = (k < HID) ? g_mi[node*HID + k] : h[node*HID + (k-HID)];
        zs[k*68 + e] = v;
    }

    u64 acc[4][8];
    float lo[8], hi[8];
    float4 wa[8];
    stage_ld<8,128>(wa, Wn1, 0, t);

    // ---- GEMM1: K=256, 8 stages ----
    zacc4x8(acc);
    #pragma unroll
    for (int s=0; s<8; s++) {
        __syncthreads();                       // s=0 also guards zs fill
        stage_st<8,128>(ws4, wa, t);
        if (s < 7) stage_ld<8,128>(wa, Wn1, 32*(s+1), t);
        else       stage_ld<8,128>(wa, Wn2, 0, t);
        __syncthreads();
        gemm_main<32,17,false>(su, ws4, tx, ty, acc, 32*s);
    }
    __syncthreads();                           // ws free + all zs reads done
    stage_st<8,128>(ws4, wa, t);
    stage_ld<8,128>(wa, Wn2, 32, t);

    // epilogue1: silu -> rewrite zs cols 0..127 as t1 (swizzled)
    #pragma unroll
    for (int p=0;p<4;p++) {
        #pragma unroll
        for (int j=0;j<8;j++) UPK2(lo[j], hi[j], acc[p][j]);
        #pragma unroll
        for (int j=0;j<8;j++) {
            float b = (j<4) ? bn1[cA+j] : bn1[cB+j-4];
            lo[j] = siluf_(lo[j] + b);
            hi[j] = siluf_(hi[j] + b);
        }
        #pragma unroll
        for (int j=0;j<8;j++) {
            u64 v; PK2(v, lo[j], hi[j]);
            int col = (j<4) ? (cA+j) : (cB+j-4);
            sts_u64(colk_addr<17>(su, col, ty, p), v);
        }
    }
    __syncthreads();                           // t1 + ws(Wn2 s0) ready

    // ---- GEMM2: K=128, 4 stages ----
    zacc4x8(acc);
    #pragma unroll
    for (int s=0; s<4; s++) {
        gemm_main<32,17,true>(su, ws4, tx, ty, acc, 32*s);
        if (s < 3) {
            __syncthreads();
            stage_st<8,128>(ws4, wa, t);
            if (s < 2) stage_ld<8,128>(wa, Wn2, 32*(s+2), t);
            __syncthreads();
        }
    }

    #pragma unroll
    for (int p=0;p<4;p++) {
        #pragma unroll
        for (int j=0;j<8;j++) UPK2(lo[j], hi[j], acc[p][j]);
        int nA = n0 + r0 + 2*p, nB = nA + 1;
        if (nA < NN) {
            float4 h0 = ld4(h + nA*HID + cA), h1 = ld4(h + nA*HID + cB);
            *(float4*)(out + nA*HID + cA) = make_float4(
                h0.x+lo[0]+bn2[cA+0], h0.y+lo[1]+bn2[cA+1],
                h0.z+lo[2]+bn2[cA+2], h0.w+lo[3]+bn2[cA+3]);
            *(float4*)(out + nA*HID + cB) = make_float4(
                h1.x+lo[4]+bn2[cB+0], h1.y+lo[5]+bn2[cB+1],
                h1.z+lo[6]+bn2[cB+2], h1.w+lo[7]+bn2[cB+3]);
        }
        if (nB < NN) {
            float4 h0 = ld4(h + nB*HID + cA), h1 = ld4(h + nB*HID + cB);
            *(float4*)(out + nB*HID + cA) = make_float4(
                h0.x+hi[0]+bn2[cA+0], h0.y+hi[1]+bn2[cA+1],
                h0.z+hi[2]+bn2[cA+2], h0.w+hi[3]+bn2[cA+3]);
            *(float4*)(out + nB*HID + cB) = make_float4(
                h1.x+hi[4]+bn2[cB+0], h1.y+hi[5]+bn2[cB+1],
                h1.z+hi[6]+bn2[cB+2], h1.w+hi[7]+bn2[cB+3]);
        }
    }
    for (int i = t; i < 64*3; i += 128) {
        int e = i/3, a = i - 3*e;
        int node = n0 + e;
        if (node < NN)
            out[XOUT_OFF + node*3 + a] = x[node*3 + a] + g_dx[node*3 + a]*mask[node];
    }
}

extern "C" void kernel_launch(void* const* d_in, const int* in_sizes, int n_in,
                              void* d_out, int out_size)
{
    const float* h         = (const float*)d_in[0];
    const float* x         = (const float*)d_in[1];
    const int*   eidx      = (const int*)d_in[2];   // int32 (jax x64 disabled)
    const float* mask      = (const float*)d_in[3];
    const float* edge_attr = (const float*)d_in[4];
    const float* We1  = (const float*)d_in[5];
    const float* be1  = (const float*)d_in[6];
    const float* We2  = (const float*)d_in[7];
    const float* be2  = (const float*)d_in[8];
    const float* Winf = (const float*)d_in[9];
    const float* binf = (const float*)d_in[10];
    const float* Wx1  = (const float*)d_in[11];
    const float* bx1  = (const float*)d_in[12];
    const float* Wx2  = (const float*)d_in[13];
    const float* Wn1  = (const float*)d_in[14];
    const float* bn1  = (const float*)d_in[15];
    const float* Wn2  = (const float*)d_in[16];
    const float* bn2  = (const float*)d_in[17];
    float* out = (float*)d_out;

    cudaFuncSetAttribute(pre_kernel,  cudaFuncAttributeMaxDynamicSharedMemorySize, PRE_SMEM);
    cudaFuncSetAttribute(edge_kernel, cudaFuncAttributeMaxDynamicSharedMemorySize, EDGE_SMEM);
    cudaFuncSetAttribute(node_kernel, cudaFuncAttributeMaxDynamicSharedMemorySize, NODE_SMEM);

    zero_kernel<<<(NN*HID/4 + 255)/256, 256>>>();
    pre_kernel <<<(NN + 63)/64, 128, PRE_SMEM>>>(h, We1);
    edge_kernel<<<NE/128, 256, EDGE_SMEM>>>(x, eidx, edge_attr,
                                            We1, be1, We2, be2, Winf, binf,
                                            Wx1, bx1, Wx2);
    node_kernel<<<(NN + 63)/64, 128, NODE_SMEM>>>(h, x, mask,
                                                  Wn1, bn1, Wn2, bn2, out);
}